// round 10
// baseline (speedup 1.0000x reference)
#include <cuda_runtime.h>
#include <cstdint>

// ICFM v7: cp.async (LDGSTS) double-buffered smem staging.
// v5 (L2 prefetch) and v6 (occupancy via reg-cap) both regressed: the reg-file
// is the wrong place to hold in-flight gather bytes. Here each warp stages its
// batch's 16 gathered rows (4KB) into private smem via cp.async.cg, issuing
// batch n+2 while computing batch n from smem. Latency tolerance = 2 full
// iterations, independent of registers/occupancy. No barriers needed: every
// lane reads back only the slots it itself staged.

#define NSEG 16384
#define UNROLL 4                 // slots; interactions/batch = 8
#define WARPS_PER_CTA 4
#define THREADS (WARPS_PER_CTA * 32)

__device__ __forceinline__ void cp16(uint32_t dst, const void* src) {
    asm volatile("cp.async.cg.shared.global [%0], [%1], 16;" :: "r"(dst), "l"(src));
}
__device__ __forceinline__ void cp_commit() {
    asm volatile("cp.async.commit_group;" ::: "memory");
}
__device__ __forceinline__ void cp_wait1() {
    asm volatile("cp.async.wait_group 1;" ::: "memory");
}

__global__ void icfm_zero(float* __restrict__ out) {
    int i = blockIdx.x * blockDim.x + threadIdx.x;
    if (i < NSEG) out[i] = 0.0f;
}

// Issue one batch's 8 row-gathers (2 per slot) into a stage buffer.
__device__ __forceinline__ void issue_batch(
    float4 (*stg)[32],               // [8][32] this warp+stage
    const float4* __restrict__ vecs,
    const int2*   __restrict__ feat_idxs,
    int b, int T, int lane, int group, int sub)
{
    const int base = b * (2 * UNROLL);
    #pragma unroll
    for (int it = 0; it < UNROLL; it++) {
        int j = base + it * 2 + group;
        int2 f = __ldg(&feat_idxs[j < T ? j : T - 1]);
        uint32_t da = (uint32_t)__cvta_generic_to_shared(&stg[it][lane]);
        uint32_t db = (uint32_t)__cvta_generic_to_shared(&stg[4 + it][lane]);
        cp16(da, &vecs[(long long)f.x * 16 + sub]);
        cp16(db, &vecs[(long long)f.y * 16 + sub]);
    }
    cp_commit();
}

__global__ void __launch_bounds__(THREADS, 7) icfm_main(
    const int*    __restrict__ intr_idxs,
    const float*  __restrict__ intr_divs,
    const int2*   __restrict__ feat_idxs,
    const int*    __restrict__ seg_ids,
    const float4* __restrict__ vecs,     // [N_FEATS, 16] as float4
    const float*  __restrict__ intr_W,
    const float*  __restrict__ intr_b,
    float*        __restrict__ out,
    int T)
{
    __shared__ float4 stg[WARPS_PER_CTA][2][8][32];   // 32 KB

    const int lane  = threadIdx.x & 31;
    const int wci   = threadIdx.x >> 5;
    const int group = lane >> 4;
    const int sub   = lane & 15;
    const int oct   = lane & 7;

    const int warp_global = blockIdx.x * WARPS_PER_CTA + wci;
    const int nwarps      = gridDim.x * WARPS_PER_CTA;
    const int nbatches    = (T + 2 * UNROLL - 1) / (2 * UNROLL);

    const float bias = __ldg(&intr_b[0]);

    int b = warp_global;
    if (b >= nbatches) return;

    // Prologue: fill both stages (or commit empty groups to keep counts aligned).
    issue_batch(stg[wci][0], vecs, feat_idxs, b, T, lane, group, sub);
    if (b + nwarps < nbatches)
        issue_batch(stg[wci][1], vecs, feat_idxs, b + nwarps, T, lane, group, sub);
    else
        cp_commit();

    int stage = 0;
    while (b < nbatches) {
        cp_wait1();   // current batch's stage complete (1 group may remain in flight)

        // Read back this lane's own staged slots.
        float4 a[UNROLL], bb[UNROLL];
        #pragma unroll
        for (int it = 0; it < UNROLL; it++) {
            a[it]  = stg[wci][stage][it][lane];
            bb[it] = stg[wci][stage][4 + it][lane];
        }

        // Lane-parallel scalars for this batch.
        const int  base   = b * (2 * UNROLL);
        const int  j2     = base + oct;
        const bool valid2 = j2 < T;
        const int  j2c    = valid2 ? j2 : T - 1;
        const int  idx    = __ldg(&intr_idxs[j2c]);
        const float dv    = __ldg(&intr_divs[j2c]);
        const int  sg     = __ldg(&seg_ids[j2c]);
        const float w     = __ldg(&intr_W[idx]);
        const float coef  = __fdividef(w, dv);

        // Re-issue this stage buffer for batch b + 2*nwarps (or empty group).
        const int b2 = b + 2 * nwarps;
        if (b2 < nbatches)
            issue_batch(stg[wci][stage], vecs, feat_idxs, b2, T, lane, group, sub);
        else
            cp_commit();

        // Dot products + reductions; route sums to owning lanes.
        float v = 0.0f;
        #pragma unroll
        for (int it = 0; it < UNROLL; it++) {
            float p = a[it].x * bb[it].x + a[it].y * bb[it].y
                    + a[it].z * bb[it].z + a[it].w * bb[it].w;
            p += __shfl_xor_sync(0xffffffffu, p, 8);
            p += __shfl_xor_sync(0xffffffffu, p, 4);
            p += __shfl_xor_sync(0xffffffffu, p, 2);
            p += __shfl_xor_sync(0xffffffffu, p, 1);
            const float q  = __shfl_xor_sync(0xffffffffu, p, 16);
            const float g0 = (lane < 16) ? p : q;
            const float g1 = (lane < 16) ? q : p;
            if ((lane & 6) == 2 * it)
                v = (lane & 1) ? g1 : g0;
        }
        v = valid2 ? (coef * v + bias) : 0.0f;

        // Segment-aggregated accumulate.
        const int      sg0 = __shfl_sync(0xffffffffu, sg, 0);
        const unsigned uni = __ballot_sync(0xffffffffu, sg == sg0);
        if (uni == 0xffffffffu) {
            v += __shfl_xor_sync(0xffffffffu, v, 4);
            v += __shfl_xor_sync(0xffffffffu, v, 2);
            v += __shfl_xor_sync(0xffffffffu, v, 1);
            if (lane == 0) atomicAdd(&out[sg0], v);
        } else {
            if (lane < 8) atomicAdd(&out[sg], v);
        }

        b += nwarps;
        stage ^= 1;
    }
}

extern "C" void kernel_launch(void* const* d_in, const int* in_sizes, int n_in,
                              void* d_out, int out_size) {
    const int*    intr_idxs = (const int*)   d_in[0];
    const float*  intr_divs = (const float*) d_in[1];
    const int2*   feat_idxs = (const int2*)  d_in[2];
    const int*    seg_ids   = (const int*)   d_in[3];
    const float4* vecs      = (const float4*)d_in[4];
    const float*  intr_W    = (const float*) d_in[5];
    const float*  intr_b    = (const float*) d_in[6];
    float*        out       = (float*)d_out;

    const int T = in_sizes[0];

    icfm_zero<<<(NSEG + 255) / 256, 256>>>(out);

    const int blocks = 148 * 7;   // 7 CTAs/SM by 32KB smem, 28 warps/SM
    icfm_main<<<blocks, THREADS>>>(intr_idxs, intr_divs, feat_idxs, seg_ids,
                                   vecs, intr_W, intr_b, out, T);
}

// round 13
// speedup vs baseline: 1.6079x; 1.6079x over previous
#include <cuda_runtime.h>

// ICFM v9: v4 skeleton (best: 54us) + multi-value butterfly reduce.
// redux.sync.add.f32 is NOT on sm_103 (v8 compile fail) — same chain-shortening
// done with plain shfls: one merging butterfly reduces all 4 slot dot-products
// simultaneously (6 shfl total vs 20), with slot index landing in lane bits
// (it = L2*2 + L3, parity = L0), so scalar ownership is re-keyed to that
// mapping and routing collapses to one select.

#define NSEG 16384
#define UNROLL 4   // slots; interactions per warp-batch = 2*UNROLL = 8
#define THREADS 128
#define FULLM 0xffffffffu

__global__ void icfm_zero(float* __restrict__ out) {
    int i = blockIdx.x * blockDim.x + threadIdx.x;
    if (i < NSEG) out[i] = 0.0f;
}

__global__ void __launch_bounds__(THREADS) icfm_main(
    const int*    __restrict__ intr_idxs,
    const float*  __restrict__ intr_divs,
    const int2*   __restrict__ feat_idxs,
    const int*    __restrict__ seg_ids,
    const float4* __restrict__ vecs,     // [N_FEATS, 16] as float4
    const float*  __restrict__ intr_W,
    const float*  __restrict__ intr_b,
    float*        __restrict__ out,
    int T)
{
    const int lane  = threadIdx.x & 31;
    const int group = lane >> 4;      // which interaction of a slot-pair (gather role)
    const int sub   = lane & 15;      // position within the 256B row

    // Ownership mapping matched to where butterfly sums land:
    //   it_own = ((lane>>2)&1)*2 + ((lane>>3)&1), parity g_own = lane&1.
    const int it_own = (((lane >> 2) & 1) << 1) | ((lane >> 3) & 1);
    const int g_own  = lane & 1;

    const int warp_global = (blockIdx.x * blockDim.x + threadIdx.x) >> 5;
    const int nwarps      = (gridDim.x * blockDim.x) >> 5;
    const int nbatches    = (T + 2 * UNROLL - 1) / (2 * UNROLL);

    const float bias = __ldg(&intr_b[0]);

    int batch = warp_global;
    if (batch >= nbatches) return;

    // Prologue: feat indices for the first batch (clamped).
    int2 fc[UNROLL];
    {
        const int base = batch * (2 * UNROLL);
        #pragma unroll
        for (int it = 0; it < UNROLL; it++) {
            int j = base + it * 2 + group;
            fc[it] = __ldg(&feat_idxs[j < T ? j : T - 1]);
        }
    }

    while (batch < nbatches) {
        const int base = batch * (2 * UNROLL);
        const int nb   = batch + nwarps;

        // 8 independent row gathers (MLP=8), issued first.
        float4 a[UNROLL], b[UNROLL];
        #pragma unroll
        for (int it = 0; it < UNROLL; it++) {
            a[it] = __ldg(&vecs[(long long)fc[it].x * 16 + sub]);
            b[it] = __ldg(&vecs[(long long)fc[it].y * 16 + sub]);
        }

        // Lane-parallel scalar loads for the interaction this lane OWNS.
        const int  j2     = base + 2 * it_own + g_own;
        const bool valid2 = j2 < T;
        const int  j2c    = valid2 ? j2 : T - 1;
        const int  idx    = __ldg(&intr_idxs[j2c]);
        const float dv    = __ldg(&intr_divs[j2c]);
        const int  sg     = __ldg(&seg_ids[j2c]);
        const float w     = __ldg(&intr_W[idx]);
        const float coef  = __fdividef(w, dv);

        // Prefetch next batch's feat indices (registers only).
        int2 fn[UNROLL];
        if (nb < nbatches) {
            const int nbase = nb * (2 * UNROLL);
            #pragma unroll
            for (int it = 0; it < UNROLL; it++) {
                int j = nbase + it * 2 + group;
                fn[it] = __ldg(&feat_idxs[j < T ? j : T - 1]);
            }
        }

        // Dot partials for all 4 slots.
        float p0 = a[0].x*b[0].x + a[0].y*b[0].y + a[0].z*b[0].z + a[0].w*b[0].w;
        float p1 = a[1].x*b[1].x + a[1].y*b[1].y + a[1].z*b[1].z + a[1].w*b[1].w;
        float p2 = a[2].x*b[2].x + a[2].y*b[2].y + a[2].z*b[2].z + a[2].w*b[2].w;
        float p3 = a[3].x*b[3].x + a[3].y*b[3].y + a[3].z*b[3].z + a[3].w*b[3].w;

        // Merging butterfly: all 4 slot sums in 5 shfls.
        const bool h8 = (lane & 8) != 0;
        const bool h4 = (lane & 4) != 0;
        float s01 = h8 ? p1 : p0;                 // keep
        float x01 = h8 ? p0 : p1;                 // send
        s01 += __shfl_xor_sync(FULLM, x01, 8);
        float s23 = h8 ? p3 : p2;
        float x23 = h8 ? p2 : p3;
        s23 += __shfl_xor_sync(FULLM, x23, 8);
        float s  = h4 ? s23 : s01;
        float x  = h4 ? s01 : s23;
        s += __shfl_xor_sync(FULLM, x, 4);
        s += __shfl_xor_sync(FULLM, s, 2);
        s += __shfl_xor_sync(FULLM, s, 1);
        // s = group-sum of slot it_own for THIS lane's group.
        const float r = __shfl_xor_sync(FULLM, s, 16);   // other group's sum
        float v = (group == g_own) ? s : r;              // full dot for owned j2
        v = valid2 ? (coef * v + bias) : 0.0f;

        // Segment-aggregated accumulate.
        const int      sg0 = __shfl_sync(FULLM, sg, 0);
        const unsigned uni = __ballot_sync(FULLM, sg == sg0);
        if (uni == FULLM) {
            // Coset over lane bits {0,2,3} holds each of the 8 interactions once.
            v += __shfl_xor_sync(FULLM, v, 1);
            v += __shfl_xor_sync(FULLM, v, 4);
            v += __shfl_xor_sync(FULLM, v, 8);
            if (lane == 0) atomicAdd(&out[sg0], v);
        } else {
            // Canonical owners: L1==0 && L4==0 — 8 lanes, one per interaction.
            if ((lane & 0x12) == 0) atomicAdd(&out[sg], v);
        }

        #pragma unroll
        for (int it = 0; it < UNROLL; it++) fc[it] = fn[it];
        batch = nb;
    }
}

extern "C" void kernel_launch(void* const* d_in, const int* in_sizes, int n_in,
                              void* d_out, int out_size) {
    const int*    intr_idxs = (const int*)   d_in[0];
    const float*  intr_divs = (const float*) d_in[1];
    const int2*   feat_idxs = (const int2*)  d_in[2];
    const int*    seg_ids   = (const int*)   d_in[3];
    const float4* vecs      = (const float4*)d_in[4];
    const float*  intr_W    = (const float*) d_in[5];
    const float*  intr_b    = (const float*) d_in[6];
    float*        out       = (float*)d_out;

    const int T = in_sizes[0];

    icfm_zero<<<(NSEG + 255) / 256, 256>>>(out);

    // Full-residency persistent grid (host-side pure query; capture-safe).
    int cta_per_sm = 0;
    cudaOccupancyMaxActiveBlocksPerMultiprocessor(&cta_per_sm, icfm_main,
                                                  THREADS, 0);
    if (cta_per_sm < 1) cta_per_sm = 8;
    const int blocks = 148 * cta_per_sm;
    icfm_main<<<blocks, THREADS>>>(intr_idxs, intr_divs, feat_idxs, seg_ids,
                                   vecs, intr_W, intr_b, out, T);
}

// round 14
// speedup vs baseline: 1.7790x; 1.1064x over previous
#include <cuda_runtime.h>

// ICFM v10: exact v4 dataflow (best: 54us) + L2 eviction-priority policies.
// v4 measurement: 9.9TB/s L2 demand, ~50% L2 hit on a 128MB table vs 126MB L2
// — streaming index arrays churn the table out. Pin table lines with
// createpolicy L2::evict_last on vec gathers; mark index/scalar streams
// L2::evict_first. v9 lesson also applied: keep the 4 INDEPENDENT shfl
// reduction trees (ILP=4 over 26-cyc SHFLs) — do not serialize them.

#define NSEG 16384
#define UNROLL 4   // slots; interactions per warp-batch = 2*UNROLL = 8

__global__ void icfm_zero(float* __restrict__ out) {
    int i = blockIdx.x * blockDim.x + threadIdx.x;
    if (i < NSEG) out[i] = 0.0f;
}

__device__ __forceinline__ unsigned long long pol_evict_last() {
    unsigned long long p;
    asm("createpolicy.fractional.L2::evict_last.b64 %0, 1.0;" : "=l"(p));
    return p;
}
__device__ __forceinline__ unsigned long long pol_evict_first() {
    unsigned long long p;
    asm("createpolicy.fractional.L2::evict_first.b64 %0, 1.0;" : "=l"(p));
    return p;
}
__device__ __forceinline__ float4 ldg_f4_hint(const float4* a, unsigned long long pol) {
    float4 v;
    asm("ld.global.nc.L2::cache_hint.v4.f32 {%0,%1,%2,%3}, [%4], %5;"
        : "=f"(v.x), "=f"(v.y), "=f"(v.z), "=f"(v.w) : "l"(a), "l"(pol));
    return v;
}
__device__ __forceinline__ int2 ldg_i2_hint(const int2* a, unsigned long long pol) {
    int2 v;
    asm("ld.global.nc.L2::cache_hint.v2.b32 {%0,%1}, [%2], %3;"
        : "=r"(v.x), "=r"(v.y) : "l"(a), "l"(pol));
    return v;
}
__device__ __forceinline__ int ldg_i_hint(const int* a, unsigned long long pol) {
    int v;
    asm("ld.global.nc.L2::cache_hint.b32 %0, [%1], %2;" : "=r"(v) : "l"(a), "l"(pol));
    return v;
}
__device__ __forceinline__ float ldg_f_hint(const float* a, unsigned long long pol) {
    float v;
    asm("ld.global.nc.L2::cache_hint.b32 %0, [%1], %2;" : "=f"(v) : "l"(a), "l"(pol));
    return v;
}

__global__ void __launch_bounds__(256, 4) icfm_main(
    const int*    __restrict__ intr_idxs,
    const float*  __restrict__ intr_divs,
    const int2*   __restrict__ feat_idxs,
    const int*    __restrict__ seg_ids,
    const float4* __restrict__ vecs,     // [N_FEATS, 16] as float4
    const float*  __restrict__ intr_W,
    const float*  __restrict__ intr_b,
    float*        __restrict__ out,
    int T)
{
    const int lane  = threadIdx.x & 31;
    const int group = lane >> 4;      // which interaction of a slot-pair
    const int sub   = lane & 15;      // position within the 256B row
    const int oct   = lane & 7;       // interaction-in-batch this lane owns

    const unsigned long long PL = pol_evict_last();   // pin: vecs table
    const unsigned long long PF = pol_evict_first();  // stream: index arrays

    const int warp_global = (blockIdx.x * blockDim.x + threadIdx.x) >> 5;
    const int nwarps      = (gridDim.x * blockDim.x) >> 5;
    const int nbatches    = (T + 2 * UNROLL - 1) / (2 * UNROLL);

    const float bias = __ldg(&intr_b[0]);

    int batch = warp_global;
    if (batch >= nbatches) return;

    // Prologue: feat indices for the first batch (clamped).
    int2 fc[UNROLL];
    {
        const int base = batch * (2 * UNROLL);
        #pragma unroll
        for (int it = 0; it < UNROLL; it++) {
            int j = base + it * 2 + group;
            fc[it] = ldg_i2_hint(&feat_idxs[j < T ? j : T - 1], PF);
        }
    }

    while (batch < nbatches) {
        const int base = batch * (2 * UNROLL);
        const int nb   = batch + nwarps;

        // 8 independent row gathers (MLP=8), table lines pinned in L2.
        float4 a[UNROLL], b[UNROLL];
        #pragma unroll
        for (int it = 0; it < UNROLL; it++) {
            a[it] = ldg_f4_hint(&vecs[(long long)fc[it].x * 16 + sub], PL);
            b[it] = ldg_f4_hint(&vecs[(long long)fc[it].y * 16 + sub], PL);
        }

        // Lane-parallel scalar loads for this batch (streaming: evict_first).
        const int  j2     = base + oct;
        const bool valid2 = j2 < T;
        const int  j2c    = valid2 ? j2 : T - 1;
        const int  idx    = ldg_i_hint(&intr_idxs[j2c], PF);
        const float dv    = ldg_f_hint(&intr_divs[j2c], PF);
        const int  sg     = ldg_i_hint(&seg_ids[j2c], PF);
        const float w     = __ldg(&intr_W[idx]);     // 4KB, stays hot anyway
        const float coef  = __fdividef(w, dv);

        // Prefetch next batch's feat indices (registers only).
        int2 fn[UNROLL];
        if (nb < nbatches) {
            const int nbase = nb * (2 * UNROLL);
            #pragma unroll
            for (int it = 0; it < UNROLL; it++) {
                int j = nbase + it * 2 + group;
                fn[it] = ldg_i2_hint(&feat_idxs[j < T ? j : T - 1], PF);
            }
        }

        // Dot products + 16-lane reductions (4 independent trees — keep ILP).
        float v = 0.0f;
        #pragma unroll
        for (int it = 0; it < UNROLL; it++) {
            float p = a[it].x * b[it].x + a[it].y * b[it].y
                    + a[it].z * b[it].z + a[it].w * b[it].w;
            p += __shfl_xor_sync(0xffffffffu, p, 8);
            p += __shfl_xor_sync(0xffffffffu, p, 4);
            p += __shfl_xor_sync(0xffffffffu, p, 2);
            p += __shfl_xor_sync(0xffffffffu, p, 1);
            const float q  = __shfl_xor_sync(0xffffffffu, p, 16);
            const float g0 = (lane < 16) ? p : q;
            const float g1 = (lane < 16) ? q : p;
            if ((lane & 6) == 2 * it)
                v = (lane & 1) ? g1 : g0;
        }
        v = valid2 ? (coef * v + bias) : 0.0f;

        // Segment-aggregated accumulate: one atomic when the batch is uniform.
        const int      sg0 = __shfl_sync(0xffffffffu, sg, 0);
        const unsigned uni = __ballot_sync(0xffffffffu, sg == sg0);
        if (uni == 0xffffffffu) {
            v += __shfl_xor_sync(0xffffffffu, v, 4);
            v += __shfl_xor_sync(0xffffffffu, v, 2);
            v += __shfl_xor_sync(0xffffffffu, v, 1);
            if (lane == 0) atomicAdd(&out[sg0], v);
        } else {
            if (lane < 8) atomicAdd(&out[sg], v);
        }

        #pragma unroll
        for (int it = 0; it < UNROLL; it++) fc[it] = fn[it];
        batch = nb;
    }
}

extern "C" void kernel_launch(void* const* d_in, const int* in_sizes, int n_in,
                              void* d_out, int out_size) {
    const int*    intr_idxs = (const int*)   d_in[0];
    const float*  intr_divs = (const float*) d_in[1];
    const int2*   feat_idxs = (const int2*)  d_in[2];
    const int*    seg_ids   = (const int*)   d_in[3];
    const float4* vecs      = (const float4*)d_in[4];
    const float*  intr_W    = (const float*) d_in[5];
    const float*  intr_b    = (const float*) d_in[6];
    float*        out       = (float*)d_out;

    const int T = in_sizes[0];

    icfm_zero<<<(NSEG + 255) / 256, 256>>>(out);

    const int blocks = 148 * 4;  // v4's proven persistent configuration
    icfm_main<<<blocks, 256>>>(intr_idxs, intr_divs, feat_idxs, seg_ids,
                               vecs, intr_W, intr_b, out, T);
}